// round 3
// baseline (speedup 1.0000x reference)
#include <cuda_runtime.h>
#include <cuda_bf16.h>

// LocallyConnected1d: out[b,c,o] = (1/8) * sum_{i<64,k<8} x[b,i,4o+k] * w[c,i,o,k]
// x: [128, 64, 1028] fp32, w: [1, 64, 64, 256, 8] fp32, out: [128, 64, 256] fp32

#define BB   128
#define CINC 64
#define COUT 64
#define OD   256
#define KW   8
#define STR  4
#define LL   1028
#define IC   8           // CIN chunk
#define RED  (IC * KW)   // 64 reduction rows per chunk

__device__ __forceinline__ void fma2(unsigned long long& acc,
                                     unsigned long long a,
                                     unsigned long long b) {
    asm("fma.rn.f32x2 %0, %1, %2, %0;" : "+l"(acc) : "l"(a), "l"(b));
}

__global__ __launch_bounds__(256, 2)
void lc1d_kernel(const float* __restrict__ x,
                 const float* __restrict__ w,
                 float* __restrict__ out) {
    __shared__ float Xs[RED][BB];    // 64 x 128 = 32 KB
    __shared__ float Ws[RED][COUT];  // 64 x 64  = 16 KB

    const int o   = blockIdx.x;
    const int tid = threadIdx.x;
    const int tb  = tid & 15;   // 16 groups along b
    const int tc  = tid >> 4;   // 16 groups along c
    const int c0  = tc * 4;

    // Per-thread tile: 4 b-pairs (b = 2*tb + 32*p + {0,1}) x 4 cout.
    // Pair base stride 32 across tb makes LDS.64 reads conflict-free.
    unsigned long long acc[4][4];
    #pragma unroll
    for (int c = 0; c < 4; c++)
        #pragma unroll
        for (int p = 0; p < 4; p++)
            acc[c][p] = 0ull;   // packed (0.0f, 0.0f)

    for (int ci = 0; ci < CINC / IC; ci++) {
        const int ibase = ci * IC;

        // ---- load X chunk: x[b, ibase+ii, 4o .. 4o+7] -> Xs[ii*8+k][b] ----
        #pragma unroll
        for (int it = 0; it < 4; it++) {
            int p  = tid + it * 256;     // 0..1023
            int b  = p & 127;
            int ii = p >> 7;
            const float4* src = reinterpret_cast<const float4*>(
                x + (size_t)(b * CINC + ibase + ii) * LL + o * STR);
            float4 v0 = src[0];
            float4 v1 = src[1];
            Xs[ii * KW + 0][b] = v0.x;  Xs[ii * KW + 1][b] = v0.y;
            Xs[ii * KW + 2][b] = v0.z;  Xs[ii * KW + 3][b] = v0.w;
            Xs[ii * KW + 4][b] = v1.x;  Xs[ii * KW + 5][b] = v1.y;
            Xs[ii * KW + 6][b] = v1.z;  Xs[ii * KW + 7][b] = v1.w;
        }

        // ---- load W chunk: w[c, ibase+ii, o, 0..7] -> Ws[ii*8+k][c] ----
        #pragma unroll
        for (int it = 0; it < 2; it++) {
            int q  = tid + it * 256;     // 0..511
            int c  = q & 63;
            int ii = q >> 6;
            const float4* src = reinterpret_cast<const float4*>(
                w + ((size_t)(c * CINC + ibase + ii) * OD + o) * KW);
            float4 v0 = src[0];
            float4 v1 = src[1];
            Ws[ii * KW + 0][c] = v0.x;  Ws[ii * KW + 1][c] = v0.y;
            Ws[ii * KW + 2][c] = v0.z;  Ws[ii * KW + 3][c] = v0.w;
            Ws[ii * KW + 4][c] = v1.x;  Ws[ii * KW + 5][c] = v1.y;
            Ws[ii * KW + 6][c] = v1.z;  Ws[ii * KW + 7][c] = v1.w;
        }

        __syncthreads();

        // ---- compute: 64 reduction rows, 16 packed FMAs each ----
        #pragma unroll 16
        for (int ik = 0; ik < RED; ik++) {
            unsigned long long xp[4];
            #pragma unroll
            for (int p = 0; p < 4; p++)
                xp[p] = *reinterpret_cast<const unsigned long long*>(
                    &Xs[ik][2 * tb + 32 * p]);

            float4 wv = *reinterpret_cast<const float4*>(&Ws[ik][c0]);
            float wf[4] = {wv.x, wv.y, wv.z, wv.w};

            #pragma unroll
            for (int c = 0; c < 4; c++) {
                unsigned long long wp;
                asm("mov.b64 %0, {%1, %1};" : "=l"(wp) : "f"(wf[c]));
                #pragma unroll
                for (int p = 0; p < 4; p++)
                    fma2(acc[c][p], xp[p], wp);
            }
        }

        __syncthreads();
    }

    // ---- epilogue: scale by 1/sqrt(64) = 0.125, scatter to out[b][c][o] ----
    const float scale = 0.125f;
    #pragma unroll
    for (int c = 0; c < 4; c++) {
        #pragma unroll
        for (int p = 0; p < 4; p++) {
            float lo, hi;
            asm("mov.b64 {%0, %1}, %2;" : "=f"(lo), "=f"(hi) : "l"(acc[c][p]));
            int b = 2 * tb + 32 * p;
            out[((size_t)b       * COUT + c0 + c) * OD + o] = lo * scale;
            out[((size_t)(b + 1) * COUT + c0 + c) * OD + o] = hi * scale;
        }
    }
}

extern "C" void kernel_launch(void* const* d_in, const int* in_sizes, int n_in,
                              void* d_out, int out_size) {
    const float* x = (const float*)d_in[0];
    const float* w = (const float*)d_in[1];
    float* out = (float*)d_out;
    lc1d_kernel<<<OD, 256>>>(x, w, out);
}

// round 6
// speedup vs baseline: 1.3253x; 1.3253x over previous
#include <cuda_runtime.h>
#include <cuda_bf16.h>
#include <cstdint>

// LocallyConnected1d: out[b,c,o] = (1/8) * sum_{i<64,k<8} x[b,i,4o+k] * w[c,i,o,k]
// x: [128, 64, 1028] fp32, w: [1, 64, 64, 256, 8] fp32, out: [128, 64, 256] fp32
//
// Per o: GEMM M=128(b), N=64(c), K=512 via mma.sync m16n8k16 bf16 (legacy HMMA,
// the only tensor path reachable through compute_103 PTX). fp32 accuracy via
// 3-term bf16 split: D = xh*wh + xh*wl + xl*wh, fp32 accumulate.

#define CINC  64
#define NCOUT 64
#define OD    256
#define KW    8
#define LL    1028

#define KC      64              // K per chunk (64 bf16 = 128 B rows, SW128)
#define NCHUNK  8               // 512 / 64

// SMEM: Ahi[128][64]bf16 | Alo | Bhi[64][64] | Blo  = 48 KB
#define A_HI  0
#define A_LO  16384
#define B_HI  32768
#define B_LO  40960
#define SMEM_BYTES 49152

#define SWZ(off) ((off) ^ ((((uint32_t)(off)) >> 3) & 0x70u))

static __device__ __forceinline__ uint32_t smem_u32(const void* p) {
    uint32_t a;
    asm("{ .reg .u64 t; cvta.to.shared.u64 t, %1; cvt.u32.u64 %0, t; }"
        : "=r"(a) : "l"(p));
    return a;
}

#define LDSM_X4(r, addr)                                                     \
    asm volatile("ldmatrix.sync.aligned.m8n8.x4.shared.b16 {%0,%1,%2,%3}, [%4];" \
        : "=r"((r)[0]), "=r"((r)[1]), "=r"((r)[2]), "=r"((r)[3]) : "r"(addr))

#define MMA_BF16(c, a, b0, b1)                                               \
    asm volatile("mma.sync.aligned.m16n8k16.row.col.f32.bf16.bf16.f32 "      \
        "{%0,%1,%2,%3}, {%4,%5,%6,%7}, {%8,%9}, {%0,%1,%2,%3};"              \
        : "+f"((c)[0]), "+f"((c)[1]), "+f"((c)[2]), "+f"((c)[3])             \
        : "r"((a)[0]), "r"((a)[1]), "r"((a)[2]), "r"((a)[3]),                \
          "r"(b0), "r"(b1))

// 8 fp32 -> 8 bf16 hi + 8 bf16 lo, stored as 16B each
static __device__ __forceinline__ void cvt_split_store(
    float4 v0, float4 v1, char* smem_base, uint32_t hi_off, uint32_t lo_off)
{
    __nv_bfloat162 h0 = __floats2bfloat162_rn(v0.x, v0.y);
    __nv_bfloat162 h1 = __floats2bfloat162_rn(v0.z, v0.w);
    __nv_bfloat162 h2 = __floats2bfloat162_rn(v1.x, v1.y);
    __nv_bfloat162 h3 = __floats2bfloat162_rn(v1.z, v1.w);

    float2 f0 = __bfloat1622float2(h0);
    float2 f1 = __bfloat1622float2(h1);
    float2 f2 = __bfloat1622float2(h2);
    float2 f3 = __bfloat1622float2(h3);

    __nv_bfloat162 l0 = __floats2bfloat162_rn(v0.x - f0.x, v0.y - f0.y);
    __nv_bfloat162 l1 = __floats2bfloat162_rn(v0.z - f1.x, v0.w - f1.y);
    __nv_bfloat162 l2 = __floats2bfloat162_rn(v1.x - f2.x, v1.y - f2.y);
    __nv_bfloat162 l3 = __floats2bfloat162_rn(v1.z - f3.x, v1.w - f3.y);

    uint4 hv, lv;
    hv.x = *reinterpret_cast<uint32_t*>(&h0);
    hv.y = *reinterpret_cast<uint32_t*>(&h1);
    hv.z = *reinterpret_cast<uint32_t*>(&h2);
    hv.w = *reinterpret_cast<uint32_t*>(&h3);
    lv.x = *reinterpret_cast<uint32_t*>(&l0);
    lv.y = *reinterpret_cast<uint32_t*>(&l1);
    lv.z = *reinterpret_cast<uint32_t*>(&l2);
    lv.w = *reinterpret_cast<uint32_t*>(&l3);

    *reinterpret_cast<uint4*>(smem_base + hi_off) = hv;
    *reinterpret_cast<uint4*>(smem_base + lo_off) = lv;
}

__global__ __launch_bounds__(256, 2)
void lc1d_mma_kernel(const float* __restrict__ x,
                     const float* __restrict__ w,
                     float* __restrict__ out)
{
    __shared__ char smem[SMEM_BYTES];
    const uint32_t sb = smem_u32(smem);

    const int o   = blockIdx.x;
    const int tid = threadIdx.x;
    const int wid = tid >> 5;
    const int lid = tid & 31;

    // warp tile: 32(m=b) x 32(n=c)
    const int m_base = (wid & 3) * 32;
    const int n_base = (wid >> 2) * 32;

    float acc[2][4][4];
    #pragma unroll
    for (int mt = 0; mt < 2; mt++)
        #pragma unroll
        for (int nt = 0; nt < 4; nt++)
            #pragma unroll
            for (int r = 0; r < 4; r++)
                acc[mt][nt][r] = 0.0f;

    // prefetch registers
    float4 xr[4][2];
    float4 wr[2][2];

    // ---- prefetch chunk 0 ----
    #pragma unroll
    for (int it = 0; it < 4; it++) {
        int p  = tid + it * 256;
        int b  = p & 127;
        int ii = p >> 7;
        const float4* src = reinterpret_cast<const float4*>(
            x + (size_t)(b * CINC + ii) * LL + o * 4);
        xr[it][0] = src[0];
        xr[it][1] = src[1];
    }
    #pragma unroll
    for (int it = 0; it < 2; it++) {
        int q  = tid + it * 256;
        int c  = q & 63;
        int ii = q >> 6;
        const float4* src = reinterpret_cast<const float4*>(
            w + ((size_t)(c * CINC + ii) * OD + o) * KW);
        wr[it][0] = src[0];
        wr[it][1] = src[1];
    }

    for (int j = 0; j < NCHUNK; j++) {
        // ---- convert prefetched chunk j -> smem (hi/lo split) ----
        #pragma unroll
        for (int it = 0; it < 4; it++) {
            int p  = tid + it * 256;
            int b  = p & 127;
            int ii = p >> 7;
            uint32_t off = SWZ((uint32_t)(b * 128 + ii * 16));
            cvt_split_store(xr[it][0], xr[it][1], smem, A_HI + off, A_LO + off);
        }
        #pragma unroll
        for (int it = 0; it < 2; it++) {
            int q  = tid + it * 256;
            int c  = q & 63;
            int ii = q >> 6;
            uint32_t off = SWZ((uint32_t)(c * 128 + ii * 16));
            cvt_split_store(wr[it][0], wr[it][1], smem, B_HI + off, B_LO + off);
        }
        __syncthreads();

        // ---- prefetch chunk j+1 (overlaps with MMA below) ----
        if (j + 1 < NCHUNK) {
            const int ibase = (j + 1) * (KC / KW);
            #pragma unroll
            for (int it = 0; it < 4; it++) {
                int p  = tid + it * 256;
                int b  = p & 127;
                int ii = p >> 7;
                const float4* src = reinterpret_cast<const float4*>(
                    x + (size_t)(b * CINC + ibase + ii) * LL + o * 4);
                xr[it][0] = src[0];
                xr[it][1] = src[1];
            }
            #pragma unroll
            for (int it = 0; it < 2; it++) {
                int q  = tid + it * 256;
                int c  = q & 63;
                int ii = q >> 6;
                const float4* src = reinterpret_cast<const float4*>(
                    w + ((size_t)(c * CINC + ibase + ii) * OD + o) * KW);
                wr[it][0] = src[0];
                wr[it][1] = src[1];
            }
        }

        // ---- MMA over 4 k16 steps of this chunk ----
        #pragma unroll
        for (int kk = 0; kk < 4; kk++) {
            uint32_t ah[2][4], al[2][4], bh[2][4], bl[2][4];

            #pragma unroll
            for (int mt = 0; mt < 2; mt++) {
                uint32_t row = (uint32_t)(m_base + mt * 16 + (lid & 15));
                uint32_t off = SWZ(row * 128 + kk * 32 + (uint32_t)(lid >> 4) * 16);
                LDSM_X4(ah[mt], sb + A_HI + off);
                LDSM_X4(al[mt], sb + A_LO + off);
            }
            #pragma unroll
            for (int nt2 = 0; nt2 < 2; nt2++) {
                uint32_t row = (uint32_t)(n_base + nt2 * 16 + (lid & 15));
                uint32_t off = SWZ(row * 128 + kk * 32 + (uint32_t)(lid >> 4) * 16);
                LDSM_X4(bh[nt2], sb + B_HI + off);
                LDSM_X4(bl[nt2], sb + B_LO + off);
            }

            #pragma unroll
            for (int mt = 0; mt < 2; mt++) {
                #pragma unroll
                for (int nt = 0; nt < 4; nt++) {
                    const int nt2 = nt >> 1;
                    const int sel = nt & 1;
                    uint32_t b0h = bh[nt2][sel], b1h = bh[nt2][sel + 2];
                    uint32_t b0l = bl[nt2][sel], b1l = bl[nt2][sel + 2];
                    MMA_BF16(acc[mt][nt], ah[mt], b0h, b1h);
                    MMA_BF16(acc[mt][nt], ah[mt], b0l, b1l);
                    MMA_BF16(acc[mt][nt], al[mt], b0h, b1h);
                }
            }
        }
        __syncthreads();
    }

    // ---- epilogue: scale by 1/sqrt(64)=0.125, scatter ----
    const float scale = 0.125f;
    const int r    = lid >> 2;
    const int col2 = (lid & 3) * 2;
    #pragma unroll
    for (int mt = 0; mt < 2; mt++) {
        #pragma unroll
        for (int nt = 0; nt < 4; nt++) {
            int b0 = m_base + mt * 16 + r;
            int n0 = n_base + nt * 8 + col2;
            out[((size_t)b0 * NCOUT + n0) * OD + o]           = acc[mt][nt][0] * scale;
            out[((size_t)b0 * NCOUT + n0 + 1) * OD + o]       = acc[mt][nt][1] * scale;
            out[((size_t)(b0 + 8) * NCOUT + n0) * OD + o]     = acc[mt][nt][2] * scale;
            out[((size_t)(b0 + 8) * NCOUT + n0 + 1) * OD + o] = acc[mt][nt][3] * scale;
        }
    }
}

extern "C" void kernel_launch(void* const* d_in, const int* in_sizes, int n_in,
                              void* d_out, int out_size) {
    const float* x = (const float*)d_in[0];
    const float* w = (const float*)d_in[1];
    float* out = (float*)d_out;
    lc1d_mma_kernel<<<OD, 256>>>(x, w, out);
}

// round 7
// speedup vs baseline: 1.3651x; 1.0301x over previous
#include <cuda_runtime.h>
#include <cuda_bf16.h>
#include <cstdint>

// LocallyConnected1d: out[b,c,o] = (1/8) * sum_{i<64,k<8} x[b,i,4o+k] * w[c,i,o,k]
// x: [128, 64, 1028] fp32, w: [1, 64, 64, 256, 8] fp32, out: [128, 64, 256] fp32
//
// Per o: GEMM M=128(b), N=64(c), K=512 via mma.sync m16n8k16 bf16 with 3-term
// bf16 split (xh*wh + xh*wl + xl*wh, fp32 acc). Double-buffered SMEM stages,
// one __syncthreads per K-chunk: convert(j+1) overlaps MMA(j) across warps.

#define CINC  64
#define NCOUT 64
#define OD    256
#define KW    8
#define LL    1028

#define KC      64              // K per chunk (64 bf16 = 128 B rows, SW128)
#define NCHUNK  8               // 512 / 64

// per-stage layout: Ahi[128][64]bf16 | Alo | Bhi[64][64] | Blo = 48 KB
#define A_HI  0
#define A_LO  16384
#define B_HI  32768
#define B_LO  40960
#define STAGE_SIZE 49152
#define SMEM_BYTES (2 * STAGE_SIZE)   // 96 KB dynamic

#define SWZ(off) ((off) ^ ((((uint32_t)(off)) >> 3) & 0x70u))

static __device__ __forceinline__ uint32_t smem_u32(const void* p) {
    uint32_t a;
    asm("{ .reg .u64 t; cvta.to.shared.u64 t, %1; cvt.u32.u64 %0, t; }"
        : "=r"(a) : "l"(p));
    return a;
}

#define LDSM_X4(r, addr)                                                     \
    asm volatile("ldmatrix.sync.aligned.m8n8.x4.shared.b16 {%0,%1,%2,%3}, [%4];" \
        : "=r"((r)[0]), "=r"((r)[1]), "=r"((r)[2]), "=r"((r)[3]) : "r"(addr))

#define MMA_BF16(c, a, b0, b1)                                               \
    asm volatile("mma.sync.aligned.m16n8k16.row.col.f32.bf16.bf16.f32 "      \
        "{%0,%1,%2,%3}, {%4,%5,%6,%7}, {%8,%9}, {%0,%1,%2,%3};"              \
        : "+f"((c)[0]), "+f"((c)[1]), "+f"((c)[2]), "+f"((c)[3])             \
        : "r"((a)[0]), "r"((a)[1]), "r"((a)[2]), "r"((a)[3]),                \
          "r"(b0), "r"(b1))

// 8 fp32 -> 8 bf16 hi + 8 bf16 lo, stored as 16 B each
static __device__ __forceinline__ void cvt_split_store(
    float4 v0, float4 v1, char* smem_base, uint32_t hi_off, uint32_t lo_off)
{
    __nv_bfloat162 h0 = __floats2bfloat162_rn(v0.x, v0.y);
    __nv_bfloat162 h1 = __floats2bfloat162_rn(v0.z, v0.w);
    __nv_bfloat162 h2 = __floats2bfloat162_rn(v1.x, v1.y);
    __nv_bfloat162 h3 = __floats2bfloat162_rn(v1.z, v1.w);

    float2 f0 = __bfloat1622float2(h0);
    float2 f1 = __bfloat1622float2(h1);
    float2 f2 = __bfloat1622float2(h2);
    float2 f3 = __bfloat1622float2(h3);

    __nv_bfloat162 l0 = __floats2bfloat162_rn(v0.x - f0.x, v0.y - f0.y);
    __nv_bfloat162 l1 = __floats2bfloat162_rn(v0.z - f1.x, v0.w - f1.y);
    __nv_bfloat162 l2 = __floats2bfloat162_rn(v1.x - f2.x, v1.y - f2.y);
    __nv_bfloat162 l3 = __floats2bfloat162_rn(v1.z - f3.x, v1.w - f3.y);

    uint4 hv, lv;
    hv.x = *reinterpret_cast<uint32_t*>(&h0);
    hv.y = *reinterpret_cast<uint32_t*>(&h1);
    hv.z = *reinterpret_cast<uint32_t*>(&h2);
    hv.w = *reinterpret_cast<uint32_t*>(&h3);
    lv.x = *reinterpret_cast<uint32_t*>(&l0);
    lv.y = *reinterpret_cast<uint32_t*>(&l1);
    lv.z = *reinterpret_cast<uint32_t*>(&l2);
    lv.w = *reinterpret_cast<uint32_t*>(&l3);

    *reinterpret_cast<uint4*>(smem_base + hi_off) = hv;
    *reinterpret_cast<uint4*>(smem_base + lo_off) = lv;
}

__global__ __launch_bounds__(256, 2)
void lc1d_mma_kernel(const float* __restrict__ x,
                     const float* __restrict__ w,
                     float* __restrict__ out)
{
    extern __shared__ char smem[];
    const uint32_t sb = smem_u32(smem);

    const int o   = blockIdx.x;
    const int tid = threadIdx.x;
    const int wid = tid >> 5;
    const int lid = tid & 31;

    // warp tile: 32(m=b) x 32(n=c)
    const int m_base = (wid & 3) * 32;
    const int n_base = (wid >> 2) * 32;

    float acc[2][4][4];
    #pragma unroll
    for (int mt = 0; mt < 2; mt++)
        #pragma unroll
        for (int nt = 0; nt < 4; nt++)
            #pragma unroll
            for (int r = 0; r < 4; r++)
                acc[mt][nt][r] = 0.0f;

    // prefetch registers
    float4 xr[4][2];
    float4 wr[2][2];

    // precomputed gather bases
    const int xb  = (tid & 127);          // b for X gather
    const int xii0 = tid >> 7;            // 0..1 ; +2 per it step of 256
    const int wc  = tid & 63;             // c for W gather
    const int wii0 = tid >> 6;            // 0..3 ; +4 per it step

    // ---- prefetch chunk 0 ----
    #pragma unroll
    for (int it = 0; it < 4; it++) {
        int ii = xii0 + it * 2;
        const float4* src = reinterpret_cast<const float4*>(
            x + (size_t)(xb * CINC + ii) * LL + o * 4);
        xr[it][0] = src[0];
        xr[it][1] = src[1];
    }
    #pragma unroll
    for (int it = 0; it < 2; it++) {
        int ii = wii0 + it * 4;
        const float4* src = reinterpret_cast<const float4*>(
            w + ((size_t)(wc * CINC + ii) * OD + o) * KW);
        wr[it][0] = __ldcs(src + 0);
        wr[it][1] = __ldcs(src + 1);
    }

    for (int j = 0; j < NCHUNK; j++) {
        const uint32_t stg = (uint32_t)(j & 1) * STAGE_SIZE;
        char* stgp = smem + stg;

        // ---- convert prefetched chunk j -> smem stage (hi/lo split) ----
        #pragma unroll
        for (int it = 0; it < 4; it++) {
            int ii = xii0 + it * 2;
            uint32_t off = SWZ((uint32_t)(xb * 128 + ii * 16));
            cvt_split_store(xr[it][0], xr[it][1], stgp, A_HI + off, A_LO + off);
        }
        #pragma unroll
        for (int it = 0; it < 2; it++) {
            int ii = wii0 + it * 4;
            uint32_t off = SWZ((uint32_t)(wc * 128 + ii * 16));
            cvt_split_store(wr[it][0], wr[it][1], stgp, B_HI + off, B_LO + off);
        }
        __syncthreads();   // single barrier per chunk (double buffer)

        // ---- issue global prefetch for chunk j+1 (hides under MMA) ----
        if (j + 1 < NCHUNK) {
            const int ibase = (j + 1) * (KC / KW);
            #pragma unroll
            for (int it = 0; it < 4; it++) {
                int ii = ibase + xii0 + it * 2;
                const float4* src = reinterpret_cast<const float4*>(
                    x + (size_t)(xb * CINC + ii) * LL + o * 4);
                xr[it][0] = src[0];
                xr[it][1] = src[1];
            }
            #pragma unroll
            for (int it = 0; it < 2; it++) {
                int ii = ibase + wii0 + it * 4;
                const float4* src = reinterpret_cast<const float4*>(
                    w + ((size_t)(wc * CINC + ii) * OD + o) * KW);
                wr[it][0] = __ldcs(src + 0);
                wr[it][1] = __ldcs(src + 1);
            }
        }

        // ---- MMA over 4 k16 steps of this chunk ----
        const uint32_t sstg = sb + stg;
        #pragma unroll
        for (int kk = 0; kk < 4; kk++) {
            uint32_t ah[2][4], al[2][4], bh[2][4], bl[2][4];

            #pragma unroll
            for (int mt = 0; mt < 2; mt++) {
                uint32_t row = (uint32_t)(m_base + mt * 16 + (lid & 15));
                uint32_t off = SWZ(row * 128 + kk * 32 + (uint32_t)(lid >> 4) * 16);
                LDSM_X4(ah[mt], sstg + A_HI + off);
                LDSM_X4(al[mt], sstg + A_LO + off);
            }
            #pragma unroll
            for (int nt2 = 0; nt2 < 2; nt2++) {
                uint32_t row = (uint32_t)(n_base + nt2 * 16 + (lid & 15));
                uint32_t off = SWZ(row * 128 + kk * 32 + (uint32_t)(lid >> 4) * 16);
                LDSM_X4(bh[nt2], sstg + B_HI + off);
                LDSM_X4(bl[nt2], sstg + B_LO + off);
            }

            #pragma unroll
            for (int mt = 0; mt < 2; mt++) {
                #pragma unroll
                for (int nt = 0; nt < 4; nt++) {
                    const int nt2 = nt >> 1;
                    const int sel = nt & 1;
                    uint32_t b0h = bh[nt2][sel], b1h = bh[nt2][sel + 2];
                    uint32_t b0l = bl[nt2][sel], b1l = bl[nt2][sel + 2];
                    MMA_BF16(acc[mt][nt], ah[mt], b0h, b1h);
                    MMA_BF16(acc[mt][nt], ah[mt], b0l, b1l);
                    MMA_BF16(acc[mt][nt], al[mt], b0h, b1h);
                }
            }
        }
        // no trailing sync: next convert writes the other stage; the single
        // sync above guarantees all reads of that stage (chunk j-1) are done.
    }

    // ---- epilogue: scale by 1/sqrt(64)=0.125, scatter ----
    const float scale = 0.125f;
    const int r    = lid >> 2;
    const int col2 = (lid & 3) * 2;
    #pragma unroll
    for (int mt = 0; mt < 2; mt++) {
        #pragma unroll
        for (int nt = 0; nt < 4; nt++) {
            int b0 = m_base + mt * 16 + r;
            int n0 = n_base + nt * 8 + col2;
            out[((size_t)b0 * NCOUT + n0) * OD + o]           = acc[mt][nt][0] * scale;
            out[((size_t)b0 * NCOUT + n0 + 1) * OD + o]       = acc[mt][nt][1] * scale;
            out[((size_t)(b0 + 8) * NCOUT + n0) * OD + o]     = acc[mt][nt][2] * scale;
            out[((size_t)(b0 + 8) * NCOUT + n0 + 1) * OD + o] = acc[mt][nt][3] * scale;
        }
    }
}

extern "C" void kernel_launch(void* const* d_in, const int* in_sizes, int n_in,
                              void* d_out, int out_size) {
    const float* x = (const float*)d_in[0];
    const float* w = (const float*)d_in[1];
    float* out = (float*)d_out;

    static int configured = 0;
    if (!configured) {
        cudaFuncSetAttribute(lc1d_mma_kernel,
                             cudaFuncAttributeMaxDynamicSharedMemorySize, SMEM_BYTES);
        configured = 1;
    }
    lc1d_mma_kernel<<<OD, 256, SMEM_BYTES>>>(x, w, out);
}